// round 12
// baseline (speedup 1.0000x reference)
#include <cuda_runtime.h>

#define NPTS  4096
#define NB    8
#define CDIM  32
#define KOUT  9
#define KALL  18
#define TSR   64            // tile rows per block
#define TSC   128           // tile cols (candidates) per step
#define NTHREADS 256
#define CAP   8

// shared memory layout (float offsets)
#define SM_QT 0
#define SM_PT (SM_QT + CDIM*TSR)           // 2048
#define SM_DT (SM_PT + CDIM*TSC)           // 6144
#define SM_RN (SM_DT + TSR*TSC)            // 14336
#define SM_CN (SM_RN + TSR)                // 14400
#define SM_QH (SM_CN + TSC)                // 14528
#define SM_BD (SM_QH + NTHREADS)           // 14784  survivor dists [CAP][256]
#define SM_BI (SM_BD + CAP*NTHREADS)       // 16832  survivor idx (short) [CAP][256]
#define SMEM_FLOATS (SM_BI + (CAP*NTHREADS)/2)   // 17856
#define SMEM_BYTES  (SMEM_FLOATS * 4)      // 71,424 bytes -> 2 blocks/SM

__device__ float g_sq[NB * NPTS];

__global__ void sqnorm_kernel(const float* __restrict__ x) {
    int idx = blockIdx.x * blockDim.x + threadIdx.x;
    if (idx >= NB * NPTS) return;
    int b = idx >> 12;
    int n = idx & (NPTS - 1);
    const float* p = x + (size_t)(b * CDIM) * NPTS + n;
    float s = 0.f;
#pragma unroll
    for (int c = 0; c < CDIM; c++) {
        float v = p[c * NPTS];
        s = fmaf(v, v, s);
    }
    g_sq[idx] = s;
}

// ---------------------------------------------------------------------------
// 64x128 tiles, 256 threads, 2 blocks/SM (register-balanced):
//  - compute: 16x16 thread grid, 4x8 fragments (32 indep FMA chains)
//  - scan A: quarter-row filter vs row-shared bound -> lane-private smem push
//    (buf[slot][tid] layout: conflict-free); CAP=8 with in-order flush
//    fallback (preserves ascending-m order -> tie semantics intact)
//  - scan B: batch insert, warp-max(cnt) network runs; +INF lanes are no-ops
//  - end: 4-way lexicographic (d, idx) merge per row == jax top_k order
// ---------------------------------------------------------------------------
__global__ __launch_bounds__(NTHREADS, 2)
void knn_kernel(const float* __restrict__ x, float* __restrict__ out) {
    extern __shared__ float sm[];
    float* qt = sm + SM_QT;   // [c][row]  32x64
    float* pt = sm + SM_PT;   // [c][cand] 32x128
    float* dt = sm + SM_DT;   // [row][cand] 64x128, chunk-swizzled
    float* rn = sm + SM_RN;
    float* cn = sm + SM_CN;
    float* qh = sm + SM_QH;   // per-quarter-thread current 18th
    float* bd = sm + SM_BD;
    short* bi = (short*)(sm + SM_BI);

    const int b    = blockIdx.y;
    const int row0 = blockIdx.x * TSR;
    const int tid  = threadIdx.x;
    const int tx   = tid & 15;          // 16 column-groups (cols 4tx.., 64+4tx..)
    const int ty   = tid >> 4;          // 16 row-groups (rows 4ty..4ty+3)
    const float* xb = x + (size_t)(b * CDIM) * NPTS;

    const int srow = tid >> 2;          // scan row (0..63)
    const int sq   = tid & 3;           // scan quarter
    const int ssw  = srow & 31;

    float dl[KALL];
    int   il[KALL];
#pragma unroll
    for (int j = 0; j < KALL; j++) { dl[j] = 3.4e38f; il[j] = 0x7FFFFFFF; }

    // sorted insert network (ascending-m call order preserves jax tie order)
    auto insert = [&](float d, int mi) {
#pragma unroll
        for (int j = KALL - 1; j >= 1; j--) {
            bool sh = d < dl[j - 1];
            bool pl = !sh && (d < dl[j]);
            float pd = dl[j - 1]; int pi = il[j - 1];
            dl[j] = sh ? pd : (pl ? d  : dl[j]);
            il[j] = sh ? pi : (pl ? mi : il[j]);
        }
        if (d < dl[0]) { dl[0] = d; il[0] = mi; }
    };

    // query tile: qt[c][r] = x[b][c][row0+r]
#pragma unroll
    for (int k = 0; k < (CDIM * TSR) / NTHREADS; k++) {
        int idx = k * NTHREADS + tid;
        qt[idx] = xb[(idx >> 6) * NPTS + row0 + (idx & 63)];
    }
    if (tid < TSR) rn[tid] = g_sq[b * NPTS + row0 + tid];
    qh[tid] = 3.4e38f;
    __syncthreads();

    for (int m0 = 0; m0 < NPTS; m0 += TSC) {
        // candidate tile
#pragma unroll
        for (int k = 0; k < (CDIM * TSC) / NTHREADS; k++) {
            int idx = k * NTHREADS + tid;
            pt[idx] = xb[(idx >> 7) * NPTS + m0 + (idx & 127)];
        }
        if (tid < TSC) cn[tid] = g_sq[b * NPTS + m0 + tid];
        __syncthreads();

        // ---- 64x128x32 inner products, 4x8 per thread ----
        float acc[4][8];
#pragma unroll
        for (int i = 0; i < 4; i++)
#pragma unroll
            for (int j = 0; j < 8; j++) acc[i][j] = 0.f;

#pragma unroll 2
        for (int c = 0; c < CDIM; c++) {
            float4 q  = *(const float4*)(qt + c * TSR + 4 * ty);
            float4 pa = *(const float4*)(pt + c * TSC + 4 * tx);
            float4 pb = *(const float4*)(pt + c * TSC + 64 + 4 * tx);
            float qv[4] = {q.x, q.y, q.z, q.w};
            float pv[8] = {pa.x, pa.y, pa.z, pa.w, pb.x, pb.y, pb.z, pb.w};
#pragma unroll
            for (int i = 0; i < 4; i++)
#pragma unroll
                for (int j = 0; j < 8; j++)
                    acc[i][j] = fmaf(qv[i], pv[j], acc[i][j]);
        }

        // ---- epilogue: d = (rn - 2*acc) + cn, swizzled float4 stores ----
        float cnv[8];
#pragma unroll
        for (int j = 0; j < 8; j++)
            cnv[j] = cn[(j < 4) ? (4 * tx + j) : (60 + 4 * tx + j)];

#pragma unroll
        for (int i = 0; i < 4; i++) {
            int r = 4 * ty + i;
            float rni = rn[r];
            float4 v0, v1;
            v0.x = (rni - 2.f * acc[i][0]) + cnv[0];
            v0.y = (rni - 2.f * acc[i][1]) + cnv[1];
            v0.z = (rni - 2.f * acc[i][2]) + cnv[2];
            v0.w = (rni - 2.f * acc[i][3]) + cnv[3];
            v1.x = (rni - 2.f * acc[i][4]) + cnv[4];
            v1.y = (rni - 2.f * acc[i][5]) + cnv[5];
            v1.z = (rni - 2.f * acc[i][6]) + cnv[6];
            v1.w = (rni - 2.f * acc[i][7]) + cnv[7];
            int sw = r & 31;
            float4* dtr = (float4*)dt + r * 32;
            dtr[tx ^ sw]        = v0;
            dtr[(16 + tx) ^ sw] = v1;
        }
        __syncthreads();

        // ---- phase A: filter quarter-row; push survivors (flush if full) ----
        {
            const float* qhr = qh + srow * 4;
            float tv = fminf(fminf(qhr[0], qhr[1]), fminf(qhr[2], qhr[3]));

            const float4* dtr = (const float4*)dt + srow * 32;
            int cnt = 0;
#pragma unroll
            for (int l = 0; l < 8; l++) {
                float4 v = dtr[(sq * 8 + l) ^ ssw];
                int mb = m0 + sq * 32 + 4 * l;
                float dv[4] = {v.x, v.y, v.z, v.w};
#pragma unroll
                for (int e = 0; e < 4; e++) {
                    float d = dv[e];
                    if (d <= tv) {   // <= keeps boundary/index-tie candidates
                        if (cnt == CAP) {   // in-order flush (tile 0 mostly)
                            for (int t = 0; t < CAP; t++)
                                insert(bd[t * NTHREADS + tid],
                                       (int)bi[t * NTHREADS + tid]);
                            cnt = 0;
                        }
                        bd[cnt * NTHREADS + tid] = d;
                        bi[cnt * NTHREADS + tid] = (short)(mb + e);
                        cnt++;
                    }
                }
            }

            // ---- phase B: batch insert, warp-max(cnt) network runs ----
            int nmax = __reduce_max_sync(0xFFFFFFFFu, cnt);
            for (int t = 0; t < nmax; t++) {
                float d  = 3.4e38f;
                int   mi = 0x7FFFFFFF;
                if (t < cnt) {
                    d  = bd[t * NTHREADS + tid];
                    mi = (int)bi[t * NTHREADS + tid];
                }
                insert(d, mi);   // +INF lanes are no-ops
            }
            qh[tid] = dl[KALL - 1];   // publish for next tile
        }
        __syncthreads();
    }

    // ---- dump quarter lists into dt region, then 4-way merge per row ----
    float* sd = dt;                       // 256*18 floats
    short* si = (short*)(dt + NTHREADS * KALL);
#pragma unroll
    for (int j = 0; j < KALL; j++) {
        sd[tid * KALL + j] = dl[j];
        si[tid * KALL + j] = (short)il[j];
    }
    __syncthreads();

    if (tid < TSR) {
        int cur[4] = {0, 0, 0, 0};
        int n = row0 + tid;
        int base0 = (b * NPTS + n) * KOUT;
        int base1 = ((NB + b) * NPTS + n) * KOUT;
#pragma unroll
        for (int t = 0; t < KALL; t++) {
            float bdv = 3.5e38f;
            int   biv = 0x7FFFFFFF;
            int   bq = 0;
#pragma unroll
            for (int q = 0; q < 4; q++) {
                int c = cur[q];
                float d2 = sd[(tid * 4 + q) * KALL + c];
                int   i2 = (int)si[(tid * 4 + q) * KALL + c];
                if (d2 < bdv || (d2 == bdv && i2 < biv)) { bdv = d2; biv = i2; bq = q; }
            }
            cur[bq]++;
            if ((t & 1) == 0) out[base0 + (t >> 1)] = (float)biv;
        }
#pragma unroll
        for (int j = 0; j < KOUT; j++) out[base1 + j] = (float)n;
    }
}

extern "C" void kernel_launch(void* const* d_in, const int* in_sizes, int n_in,
                              void* d_out, int out_size) {
    const float* x = (const float*)d_in[0];
    float* out = (float*)d_out;

    cudaFuncSetAttribute(knn_kernel, cudaFuncAttributeMaxDynamicSharedMemorySize,
                         SMEM_BYTES);

    sqnorm_kernel<<<(NB * NPTS + 255) / 256, 256>>>(x);

    dim3 grid(NPTS / TSR, NB);
    knn_kernel<<<grid, NTHREADS, SMEM_BYTES>>>(x, out);
}

// round 13
// speedup vs baseline: 1.4140x; 1.4140x over previous
#include <cuda_runtime.h>

#define NPTS  4096
#define NB    8
#define CDIM  32
#define KOUT  9
#define KALL  18
#define TILE  128
#define NTHREADS 512
#define CAP   32

// shared memory layout (float offsets)
#define SM_QT 0
#define SM_PT (SM_QT + CDIM*TILE)            // 4096   pt[2][32][128]
#define SM_DT (SM_PT + 2*CDIM*TILE)          // 12288
#define SM_RN (SM_DT + TILE*TILE)            // 28672
#define SM_CN (SM_RN + TILE)                 // 28800  cn[2][128]
#define SM_QH (SM_CN + 2*TILE)               // 29056
#define SM_BD (SM_QH + NTHREADS)             // 29568
#define SM_BI (SM_BD + CAP*NTHREADS)         // 45952
#define SMEM_FLOATS (SM_BI + (CAP*NTHREADS)/2)   // 54144
#define SMEM_BYTES  (SMEM_FLOATS * 4)        // 216,576 bytes

__device__ float g_sq[NB * NPTS];

__global__ void sqnorm_kernel(const float* __restrict__ x) {
    int idx = blockIdx.x * blockDim.x + threadIdx.x;
    if (idx >= NB * NPTS) return;
    int b = idx >> 12;
    int n = idx & (NPTS - 1);
    const float* p = x + (size_t)(b * CDIM) * NPTS + n;
    float s = 0.f;
#pragma unroll
    for (int c = 0; c < CDIM; c++) {
        float v = p[c * NPTS];
        s = fmaf(v, v, s);
    }
    g_sq[idx] = s;
}

__device__ __forceinline__ void ffma2(unsigned long long& acc,
                                      unsigned long long a,
                                      unsigned long long b) {
    asm("fma.rn.f32x2 %0, %1, %2, %0;" : "+l"(acc) : "l"(a), "l"(b));
}
__device__ __forceinline__ unsigned long long packdup(float v) {
    unsigned long long r;
    asm("mov.b64 %0, {%1, %1};" : "=l"(r) : "r"(__float_as_uint(v)));
    return r;
}
__device__ __forceinline__ void unpack2(unsigned long long v, float& lo, float& hi) {
    unsigned int a, b;
    asm("mov.b64 {%0, %1}, %2;" : "=r"(a), "=r"(b) : "l"(v));
    lo = __uint_as_float(a); hi = __uint_as_float(b);
}

// ---------------------------------------------------------------------------
// 128x128 tiles, 512 threads (R11 skeleton + FFMA2 + warp-private scan):
//  - compute: 32x16 grid, 4x8 fragments as 4x4 f32x2 pairs (fma.rn.f32x2:
//    2 FMAs/slot, bit-identical per lane to scalar fmaf)
//  - dt rows 8w..8w+7 are written AND scanned by warp w -> the epilogue/scan
//    barriers become __syncwarp; qh is warp-private too
//  - pt/cn double-buffered: ONE __syncthreads per tile; next tile's GMEM
//    loads issued before compute
//  - scan: filter vs row-shared bound -> lane-private smem push (CAP=32),
//    then batch insert warp-max(cnt) times (+INF lanes no-op)
//  - end: 4-way lexicographic (d, idx) merge per row == jax top_k order
// ---------------------------------------------------------------------------
__global__ __launch_bounds__(NTHREADS, 1)
void knn_kernel(const float* __restrict__ x, float* __restrict__ out) {
    extern __shared__ float sm[];
    float* qt = sm + SM_QT;
    float* ptb = sm + SM_PT;   // [2][32][128]
    float* dt = sm + SM_DT;
    float* rn = sm + SM_RN;
    float* cnb = sm + SM_CN;   // [2][128]
    float* qh = sm + SM_QH;
    float* bd = sm + SM_BD;
    short* bi = (short*)(sm + SM_BI);

    const int b    = blockIdx.y;
    const int row0 = blockIdx.x * TILE;
    const int tid  = threadIdx.x;
    const int tx   = tid & 15;
    const int ty   = tid >> 4;
    const float* xb = x + (size_t)(b * CDIM) * NPTS;

    const int srow = tid >> 2;
    const int sq   = tid & 3;
    const int ssw  = srow & 31;

    float dl[KALL];
    int   il[KALL];
#pragma unroll
    for (int j = 0; j < KALL; j++) { dl[j] = 3.4e38f; il[j] = 0x7FFFFFFF; }

#pragma unroll
    for (int k = 0; k < (CDIM * TILE) / NTHREADS; k++) {
        int idx = k * NTHREADS + tid;
        qt[idx] = xb[(idx >> 7) * NPTS + row0 + (idx & 127)];
    }
    if (tid < TILE) rn[tid] = g_sq[b * NPTS + row0 + tid];
    qh[tid] = 3.4e38f;
    // prologue: load tile 0 into buffer 0
#pragma unroll
    for (int k = 0; k < (CDIM * TILE) / NTHREADS; k++) {
        int idx = k * NTHREADS + tid;
        ptb[idx] = xb[(idx >> 7) * NPTS + (idx & 127)];
    }
    if (tid < TILE) cnb[tid] = g_sq[b * NPTS + tid];
    __syncthreads();

    for (int t = 0; t < NPTS / TILE; t++) {
        const int cur = t & 1;
        float* pt = ptb + cur * CDIM * TILE;
        float* cn = cnb + cur * TILE;
        const int m0 = t * TILE;

        // issue next tile's loads (hidden behind compute)
        if (t < NPTS / TILE - 1) {
            float* ptn = ptb + (cur ^ 1) * CDIM * TILE;
            int m1 = m0 + TILE;
#pragma unroll
            for (int k = 0; k < (CDIM * TILE) / NTHREADS; k++) {
                int idx = k * NTHREADS + tid;
                ptn[idx] = xb[(idx >> 7) * NPTS + m1 + (idx & 127)];
            }
            if (tid < TILE) cnb[(cur ^ 1) * TILE + tid] = g_sq[b * NPTS + m1 + tid];
        }

        // ---- 128x128x32 inner products: 4 rows x 4 col-pairs of f32x2 ----
        unsigned long long acc2[4][4];
#pragma unroll
        for (int i = 0; i < 4; i++)
#pragma unroll
            for (int j = 0; j < 4; j++) acc2[i][j] = 0ull;

#pragma unroll 2
        for (int c = 0; c < CDIM; c++) {
            float4 q = *(const float4*)(qt + c * TILE + 4 * ty);
            ulonglong2 pA = *(const ulonglong2*)(pt + c * TILE + 4 * tx);
            ulonglong2 pB = *(const ulonglong2*)(pt + c * TILE + 64 + 4 * tx);
            unsigned long long qq[4] = {packdup(q.x), packdup(q.y),
                                        packdup(q.z), packdup(q.w)};
#pragma unroll
            for (int i = 0; i < 4; i++) {
                ffma2(acc2[i][0], qq[i], pA.x);
                ffma2(acc2[i][1], qq[i], pA.y);
                ffma2(acc2[i][2], qq[i], pB.x);
                ffma2(acc2[i][3], qq[i], pB.y);
            }
        }

        // ---- epilogue: d = (rn - 2*acc) + cn, swizzled float4 stores ----
        float cnv[8];
#pragma unroll
        for (int j = 0; j < 8; j++)
            cnv[j] = cn[(j < 4) ? (4 * tx + j) : (60 + 4 * tx + j)];

#pragma unroll
        for (int i = 0; i < 4; i++) {
            int r = 4 * ty + i;
            float rni = rn[r];
            float a0, a1, a2, a3, a4, a5, a6, a7;
            unpack2(acc2[i][0], a0, a1);
            unpack2(acc2[i][1], a2, a3);
            unpack2(acc2[i][2], a4, a5);
            unpack2(acc2[i][3], a6, a7);
            float4 v0, v1;
            v0.x = (rni - 2.f * a0) + cnv[0];
            v0.y = (rni - 2.f * a1) + cnv[1];
            v0.z = (rni - 2.f * a2) + cnv[2];
            v0.w = (rni - 2.f * a3) + cnv[3];
            v1.x = (rni - 2.f * a4) + cnv[4];
            v1.y = (rni - 2.f * a5) + cnv[5];
            v1.z = (rni - 2.f * a6) + cnv[6];
            v1.w = (rni - 2.f * a7) + cnv[7];
            int sw = r & 31;
            float4* dtr = (float4*)dt + r * 32;
            dtr[tx ^ sw]        = v0;
            dtr[(16 + tx) ^ sw] = v1;
        }
        __syncwarp();   // dt rows for this warp are warp-private

        // ---- phase A: filter quarter-row vs row-shared bound ----
        {
            const float* qhr = qh + srow * 4;
            float tv = fminf(fminf(qhr[0], qhr[1]), fminf(qhr[2], qhr[3]));

            const float4* dtr = (const float4*)dt + srow * 32;
            int cnt = 0;
#pragma unroll
            for (int l = 0; l < 8; l++) {
                float4 v = dtr[(sq * 8 + l) ^ ssw];
                int mb = m0 + sq * 32 + 4 * l;
                float dv[4] = {v.x, v.y, v.z, v.w};
#pragma unroll
                for (int e = 0; e < 4; e++) {
                    float d = dv[e];
                    if (d <= tv) {
                        bd[cnt * NTHREADS + tid] = d;
                        bi[cnt * NTHREADS + tid] = (short)(mb + e);
                        cnt++;
                    }
                }
            }

            // ---- phase B: batch insert, warp-max(cnt) network runs ----
            int nmax = __reduce_max_sync(0xFFFFFFFFu, cnt);
            for (int s = 0; s < nmax; s++) {
                float d  = 3.4e38f;
                int   mi = 0x7FFFFFFF;
                if (s < cnt) {
                    d  = bd[s * NTHREADS + tid];
                    mi = (int)bi[s * NTHREADS + tid];
                }
                // branch-free sorted insert; +INF lanes are no-ops
#pragma unroll
                for (int j = KALL - 1; j >= 1; j--) {
                    bool sh = d < dl[j - 1];
                    bool pl = !sh && (d < dl[j]);
                    float pd = dl[j - 1]; int pi = il[j - 1];
                    dl[j] = sh ? pd : (pl ? d  : dl[j]);
                    il[j] = sh ? pi : (pl ? mi : il[j]);
                }
                if (d < dl[0]) { dl[0] = d; il[0] = mi; }
            }
            qh[tid] = dl[KALL - 1];   // warp-private publish
        }
        __syncthreads();   // next-buffer loads visible; cur free to overwrite
    }

    // ---- dump quarter lists into dt region, then 4-way merge per row ----
    float* sd = dt;
    short* si = (short*)(dt + NTHREADS * KALL);
#pragma unroll
    for (int j = 0; j < KALL; j++) {
        sd[tid * KALL + j] = dl[j];
        si[tid * KALL + j] = (short)il[j];
    }
    __syncthreads();

    if (tid < TILE) {
        int cur4[4] = {0, 0, 0, 0};
        int n = row0 + tid;
        int base0 = (b * NPTS + n) * KOUT;
        int base1 = ((NB + b) * NPTS + n) * KOUT;
#pragma unroll
        for (int t = 0; t < KALL; t++) {
            float bdv = 3.5e38f;
            int   biv = 0x7FFFFFFF;
            int   bq = 0;
#pragma unroll
            for (int q = 0; q < 4; q++) {
                int c = cur4[q];
                float d2 = sd[(tid * 4 + q) * KALL + c];
                int   i2 = (int)si[(tid * 4 + q) * KALL + c];
                if (d2 < bdv || (d2 == bdv && i2 < biv)) { bdv = d2; biv = i2; bq = q; }
            }
            cur4[bq]++;
            if ((t & 1) == 0) out[base0 + (t >> 1)] = (float)biv;
        }
#pragma unroll
        for (int j = 0; j < KOUT; j++) out[base1 + j] = (float)n;
    }
}

extern "C" void kernel_launch(void* const* d_in, const int* in_sizes, int n_in,
                              void* d_out, int out_size) {
    const float* x = (const float*)d_in[0];
    float* out = (float*)d_out;

    cudaFuncSetAttribute(knn_kernel, cudaFuncAttributeMaxDynamicSharedMemorySize,
                         SMEM_BYTES);

    sqnorm_kernel<<<(NB * NPTS + 511) / 512, 512>>>(x);

    dim3 grid(NPTS / TILE, NB);
    knn_kernel<<<grid, NTHREADS, SMEM_BYTES>>>(x, out);
}